// round 15
// baseline (speedup 1.0000x reference)
#include <cuda_runtime.h>
#include <cuda_fp8.h>
#include <cstdint>
#include <math.h>

// ---------------------------------------------------------------------------
// Problem constants (fixed shapes: x,y = [4096,1024] fp32, scalar output)
// ---------------------------------------------------------------------------
#define BROWS 4096
#define DDIM  1024
#define EPSF  1e-6f

// fp8 quantization pre-scale: e4m3 of 16*component; acc = 256*S.
// exp(S/tau) = exp2(acc * log2(e) / (0.07 * 256))
#define QSCALE 16.0f
#define K2LOG_S (20.6099287984152302f / 256.0f)

// R14 analysis: per-SMSP QMMA issue interval ~29 cyc with only 4 warps/SMSP
// (per-warp blocking ~116 cyc). R15 tests the warp-count hypothesis: 1024
// threads/CTA -> 8 warps/SMSP, warp tile 16x32 (acc 16 regs, fits 64-reg cap).
#define BM 128
#define BN 128
#define BK 128
#define KT 8
#define STAGES 4
#define RS (BK + 16)
#define STAGE_BYTES ((BM + BN) * RS)             // 36864
#define SMEM_BYTES (STAGES * STAGE_BYTES)        // 147456
#define NSM 148
#define NTILES 1024
#define NTHR 1024

// ---------------------------------------------------------------------------
// Scratch (device globals: allocation-free rule; zero-initialized)
// ---------------------------------------------------------------------------
__device__ uint8_t g_xq[(size_t)BROWS * DDIM];
__device__ uint8_t g_yq[(size_t)BROWS * DDIM];
__device__ float g_rowsum[BROWS];
__device__ float g_colsum[BROWS];
__device__ float g_diag[BROWS];
__device__ int g_cnt[32];     // row blocks of 128; ==128 when block ready
__device__ int g_done;        // CTA completion counter

// ---------------------------------------------------------------------------
// PTX helpers (<= sm_89; nothing 'a'-gated)
// ---------------------------------------------------------------------------
static __device__ __forceinline__ uint32_t smem_u32(const void* p) {
    uint32_t a;
    asm("{ .reg .u64 t; cvta.to.shared.u64 t, %1; cvt.u32.u64 %0, t; }"
        : "=r"(a) : "l"(p));
    return a;
}
static __device__ __forceinline__ float ex2f(float x) {
    float y;
    asm("ex2.approx.ftz.f32 %0, %1;" : "=f"(y) : "f"(x));
    return y;
}
static __device__ __forceinline__ void cp16(uint32_t dst, const void* src) {
    asm volatile("cp.async.cg.shared.global [%0], [%1], 16;"
                 :: "r"(dst), "l"(src) : "memory");
}
#define CP_COMMIT() asm volatile("cp.async.commit_group;" ::: "memory")
#define CP_WAIT(n)  asm volatile("cp.async.wait_group %0;" :: "n"(n) : "memory")

static __device__ __forceinline__ void ldmatrix_x4(
    uint32_t& r0, uint32_t& r1, uint32_t& r2, uint32_t& r3, uint32_t addr) {
    asm volatile("ldmatrix.sync.aligned.m8n8.x4.shared.b16 {%0,%1,%2,%3}, [%4];"
                 : "=r"(r0), "=r"(r1), "=r"(r2), "=r"(r3) : "r"(addr));
}
static __device__ __forceinline__ void mma16832(
    float* d, const uint32_t* a, const uint32_t* b) {
    asm volatile(
        "mma.sync.aligned.m16n8k32.row.col.f32.e4m3.e4m3.f32 "
        "{%0,%1,%2,%3}, {%4,%5,%6,%7}, {%8,%9}, {%0,%1,%2,%3};"
        : "+f"(d[0]), "+f"(d[1]), "+f"(d[2]), "+f"(d[3])
        : "r"(a[0]), "r"(a[1]), "r"(a[2]), "r"(a[3]), "r"(b[0]), "r"(b[1]));
}
static __device__ __forceinline__ uint32_t pack_fp8x4(
    float a, float b, float c, float d) {
    const __nv_fp8x2_storage_t lo =
        __nv_cvt_float2_to_fp8x2(make_float2(a, b), __NV_SATFINITE, __NV_E4M3);
    const __nv_fp8x2_storage_t hi =
        __nv_cvt_float2_to_fp8x2(make_float2(c, d), __NV_SATFINITE, __NV_E4M3);
    return (uint32_t)lo | ((uint32_t)hi << 16);
}

// tid 0 spins; caller must follow with __syncthreads() before consuming.
static __device__ __forceinline__ void wait_blocks_t0(int xb, int yb, int tid) {
    if (tid == 0) {
        volatile int* c = g_cnt;
        while (c[xb] != 128) {}
        while (c[yb] != 128) {}
        __threadfence();
    }
}

// A: 1024 cp16, B: 1024 cp16 -> one each per thread at 1024 threads
static __device__ __forceinline__ void load_chunk(
    uint32_t sbase, int stage, int chunk,
    const uint8_t* gA, const uint8_t* gB, int tid) {
    const uint32_t aBase = sbase + (uint32_t)(stage * STAGE_BYTES);
    const uint32_t bBase = aBase + (uint32_t)(BM * RS);
    const int row = tid >> 3, c = tid & 7;
    cp16(aBase + (uint32_t)(row * RS + c * 16),
         gA + (size_t)(chunk * BK) + (size_t)row * DDIM + c * 16);
    cp16(bBase + (uint32_t)(row * RS + c * 16),
         gB + (size_t)(chunk * BK) + (size_t)row * DDIM + c * 16);
    CP_COMMIT();
}

// one kk step: A m16k32 = 1 ldmatrix.x4; B 32 cols = 2 ldmatrix.x4
static __device__ __forceinline__ void load_frags(
    uint32_t aAddr0, uint32_t bAddr0, uint32_t kb,
    uint32_t a[4], uint32_t b[4][2]) {
    ldmatrix_x4(a[0], a[1], a[2], a[3], aAddr0 + kb);
#pragma unroll
    for (int p2 = 0; p2 < 2; ++p2) {
        uint32_t r0, r1, r2, r3;
        ldmatrix_x4(r0, r1, r2, r3, bAddr0 + kb + (uint32_t)(p2 * 16 * RS));
        b[2 * p2][0] = r0; b[2 * p2 + 1][0] = r1;
        b[2 * p2][1] = r2; b[2 * p2 + 1][1] = r3;
    }
}

// ---------------------------------------------------------------------------
// The fused persistent kernel: grid = 148 x 1024 threads
// ---------------------------------------------------------------------------
__global__ void __launch_bounds__(NTHR, 1) fused_kernel(
    const float* __restrict__ x, const float* __restrict__ y,
    float* __restrict__ out) {
    extern __shared__ uint8_t smem[];
    __shared__ float part[4][8][3];     // 4 rows x 8 warps x {ssx,ssy,sxy}
    __shared__ int sdone;
    const uint32_t sbase = smem_u32(smem);
    const int tid = threadIdx.x;
    const int lane = tid & 31;
    const int wid = tid >> 5;

    // ========== Phase A: normalize + quantize (256 threads per row) =========
    // Each iteration handles 4 rows; thread owns 1 float4 of x and y (8 regs).
    for (int g = blockIdx.x; g < BROWS / 4; g += NSM) {
        const int rg = tid >> 8;            // row-in-group 0..3
        const int pos = tid & 255;          // float4 index within row
        const int r = g * 4 + rg;
        const float4 xv = reinterpret_cast<const float4*>(x)[(size_t)r * 256 + pos];
        const float4 yv = reinterpret_cast<const float4*>(y)[(size_t)r * 256 + pos];

        float ssx = xv.x * xv.x + xv.y * xv.y + xv.z * xv.z + xv.w * xv.w;
        float ssy = yv.x * yv.x + yv.y * yv.y + yv.z * yv.z + yv.w * yv.w;
        float sxy = xv.x * yv.x + xv.y * yv.y + xv.z * yv.z + xv.w * yv.w;
#pragma unroll
        for (int m = 16; m; m >>= 1) {
            ssx += __shfl_xor_sync(0xffffffffu, ssx, m);
            ssy += __shfl_xor_sync(0xffffffffu, ssy, m);
            sxy += __shfl_xor_sync(0xffffffffu, sxy, m);
        }
        if (lane == 0) {
            part[rg][(pos >> 5)][0] = ssx;
            part[rg][(pos >> 5)][1] = ssy;
            part[rg][(pos >> 5)][2] = sxy;
        }
        __syncthreads();
        float a = 0.f, b = 0.f, c = 0.f;
#pragma unroll
        for (int w = 0; w < 8; ++w) {
            a += part[rg][w][0]; b += part[rg][w][1]; c += part[rg][w][2];
        }
        const float invx = 1.0f / fmaxf(sqrtf(a), EPSF);
        const float invy = 1.0f / fmaxf(sqrtf(b), EPSF);
        if (pos == 0) {
            g_diag[r] = c * invx * invy;
            g_rowsum[r] = 0.f;
            g_colsum[r] = 0.f;
        }
        const float qx = QSCALE * invx, qy = QSCALE * invy;
        reinterpret_cast<uint32_t*>(g_xq + (size_t)r * DDIM)[pos] =
            pack_fp8x4(xv.x * qx, xv.y * qx, xv.z * qx, xv.w * qx);
        reinterpret_cast<uint32_t*>(g_yq + (size_t)r * DDIM)[pos] =
            pack_fp8x4(yv.x * qy, yv.y * qy, yv.z * qy, yv.w * qy);
        __threadfence();
        __syncthreads();                 // all stores fenced; partials reusable
        if (pos == 0) atomicAdd(&g_cnt[r >> 7], 1);
    }

    // ================= Phase B: persistent GEMM, warp tile 16x32 ============
    const int warp_m = wid & 7;          // 16-row slice
    const int warp_n = wid >> 3;         // 32-col slice
    const int gid = lane >> 2, tig = lane & 3;
    const uint32_t lrow = (uint32_t)(lane & 15);
    const uint32_t koff = (uint32_t)((lane >> 4) * 16);

    int t = blockIdx.x;
    const uint8_t* gA = g_xq + (size_t)((t & 31) * BM) * DDIM;
    const uint8_t* gB = g_yq + (size_t)((t >> 5) * BN) * DDIM;

    wait_blocks_t0(t & 31, t >> 5, tid);
    __syncthreads();
    load_chunk(sbase, 0, 0, gA, gB, tid);
    load_chunk(sbase, 1, 1, gA, gB, tid);
    load_chunk(sbase, 2, 2, gA, gB, tid);

    while (true) {
        const int i_base = (t & 31) * BM;
        const int j_base = (t >> 5) * BN;
        const int nxt = t + NSM;
        const bool has_nxt = (nxt < NTILES);
        const uint8_t* gA2 = g_xq + (size_t)((nxt & 31) * BM) * DDIM;
        const uint8_t* gB2 = g_yq + (size_t)((nxt >> 5) * BN) * DDIM;

        float acc[4][4];
#pragma unroll
        for (int ni = 0; ni < 4; ++ni)
#pragma unroll
            for (int r = 0; r < 4; ++r) acc[ni][r] = 0.f;

        for (int kt = 0; kt < KT; ++kt) {
            CP_WAIT(STAGES - 2);
            __syncthreads();
            const int p = kt + STAGES - 1;
            if (p < KT) {
                load_chunk(sbase, p & 3, p, gA, gB, tid);
            } else if (has_nxt) {
                if (kt == 5) {
                    wait_blocks_t0(nxt & 31, nxt >> 5, tid);
                    __syncthreads();
                }
                load_chunk(sbase, p & 3, p - KT, gA2, gB2, tid);
            } else {
                CP_COMMIT();
            }

            const uint32_t aTile = sbase + (uint32_t)((kt & 3) * STAGE_BYTES);
            const uint32_t bTile = aTile + (uint32_t)(BM * RS);
            const uint32_t aAddr0 = aTile + (warp_m * 16 + lrow) * RS + koff;
            const uint32_t bAddr0 = bTile + (warp_n * 32 + lrow) * RS + koff;

            uint32_t a[2][4], b[2][4][2];
            load_frags(aAddr0, bAddr0, 0, a[0], b[0]);

#pragma unroll
            for (int kk = 0; kk < 4; ++kk) {
                const int cur = kk & 1;
                if (kk < 3)
                    load_frags(aAddr0, bAddr0, (uint32_t)((kk + 1) * 32),
                               a[cur ^ 1], b[cur ^ 1]);
#pragma unroll
                for (int ni = 0; ni < 4; ++ni)
                    mma16832(acc[ni], a[cur], b[cur][ni]);
            }
        }

        // -------- fused epilogue: exp + row/col sums --------
        float rs[2] = {0.f, 0.f};
        float cs[4][2];
#pragma unroll
        for (int ni = 0; ni < 4; ++ni) { cs[ni][0] = 0.f; cs[ni][1] = 0.f; }

#pragma unroll
        for (int ni = 0; ni < 4; ++ni) {
            const float e0 = ex2f(acc[ni][0] * K2LOG_S);
            const float e1 = ex2f(acc[ni][1] * K2LOG_S);
            const float e2 = ex2f(acc[ni][2] * K2LOG_S);
            const float e3 = ex2f(acc[ni][3] * K2LOG_S);
            rs[0] += e0 + e1;            // row = m0 + gid
            rs[1] += e2 + e3;            // row + 8
            cs[ni][0] += e0 + e2;        // col = n0 + ni*8 + 2*tig
            cs[ni][1] += e1 + e3;
        }

        const int m0 = i_base + warp_m * 16;
        const int n0 = j_base + warp_n * 32;
#pragma unroll
        for (int h = 0; h < 2; ++h) {
            float v = rs[h];
            v += __shfl_xor_sync(0xffffffffu, v, 1);
            v += __shfl_xor_sync(0xffffffffu, v, 2);
            if (tig == 0)
                atomicAdd(&g_rowsum[m0 + h * 8 + gid], v);
        }
#pragma unroll
        for (int ni = 0; ni < 4; ++ni)
#pragma unroll
            for (int h = 0; h < 2; ++h) {
                float v = cs[ni][h];
                v += __shfl_xor_sync(0xffffffffu, v, 4);
                v += __shfl_xor_sync(0xffffffffu, v, 8);
                v += __shfl_xor_sync(0xffffffffu, v, 16);
                if (gid == 0)
                    atomicAdd(&g_colsum[n0 + ni * 8 + 2 * tig + h], v);
            }

        if (!has_nxt) break;
        t = nxt;
        gA = gA2;
        gB = gB2;
    }

    // ================= Phase C: last CTA finalizes + resets =================
    __threadfence();
    __syncthreads();
    if (tid == 0) sdone = (atomicAdd(&g_done, 1) == NSM - 1) ? 1 : 0;
    __syncthreads();
    if (sdone) {
        __threadfence();
        const float extra = (float)BROWS * 1e-6f + 1e-6f;
        float acc = 0.f;
#pragma unroll
        for (int i = tid; i < BROWS; i += NTHR) {
            acc += (2.0f / 0.07f) * g_diag[i]
                 - logf(g_rowsum[i] + extra)
                 - logf(g_colsum[i] + extra);
        }
        float* sb = reinterpret_cast<float*>(smem);
        sb[tid] = acc;
        __syncthreads();
#pragma unroll
        for (int s = 512; s; s >>= 1) {
            if (tid < s) sb[tid] += sb[tid + s];
            __syncthreads();
        }
        if (tid == 0) out[0] = sb[0] * (-1.0f / (2.0f * (float)BROWS));
        // reset handshake state for the next graph replay
        if (tid < 32) g_cnt[tid] = 0;
        if (tid == 0) g_done = 0;
    }
}

// ---------------------------------------------------------------------------
extern "C" void kernel_launch(void* const* d_in, const int* in_sizes, int n_in,
                              void* d_out, int out_size) {
    const float* x = (const float*)d_in[0];
    const float* y = (const float*)d_in[1];
    float* out = (float*)d_out;

    static int configured = 0;
    if (!configured) {
        cudaFuncSetAttribute(fused_kernel,
                             cudaFuncAttributeMaxDynamicSharedMemorySize, SMEM_BYTES);
        configured = 1;
    }

    fused_kernel<<<NSM, NTHR, SMEM_BYTES>>>(x, y, out);
}

// round 16
// speedup vs baseline: 1.0923x; 1.0923x over previous
#include <cuda_runtime.h>
#include <cuda_fp8.h>
#include <cstdint>
#include <math.h>

// ---------------------------------------------------------------------------
// Problem constants (fixed shapes: x,y = [4096,1024] fp32, scalar output)
// ---------------------------------------------------------------------------
#define BROWS 4096
#define DDIM  1024
#define EPSF  1e-6f

// fp8 quantization pre-scale: e4m3 of 16*component; acc = 256*S.
// exp(S/tau) = exp2(acc * log2(e) / (0.07 * 256))
#define QSCALE 16.0f
#define K2LOG_S (20.6099287984152302f / 256.0f)

// R15 conclusion: legacy mma.sync has a hard ~29 cyc/instruction/SMSP floor;
// R12/R14 GEMM sits on it (~114us). Remaining slack = phase A (~12us vs ~6us
// HBM floor). R16 = R14 GEMM verbatim + phase A rebuilt as 4-rows-per-CTA
// iteration, 128 threads/row (2 float4 per tensor per thread, 2 syncs/4 rows,
// coalesced u32 stores, batched fences).
#define BM 128
#define BN 128
#define BK 128
#define KT 8
#define STAGES 4
#define RS (BK + 16)
#define STAGE_BYTES ((BM + BN) * RS)             // 36864
#define SMEM_BYTES (STAGES * STAGE_BYTES)        // 147456
#define NSM 148
#define NTILES 1024

// ---------------------------------------------------------------------------
// Scratch (device globals: allocation-free rule; zero-initialized)
// ---------------------------------------------------------------------------
__device__ uint8_t g_xq[(size_t)BROWS * DDIM];
__device__ uint8_t g_yq[(size_t)BROWS * DDIM];
__device__ float g_rowsum[BROWS];
__device__ float g_colsum[BROWS];
__device__ float g_diag[BROWS];
__device__ int g_cnt[32];     // row blocks of 128; ==128 when block ready
__device__ int g_done;        // CTA completion counter

// ---------------------------------------------------------------------------
// PTX helpers (<= sm_89; nothing 'a'-gated)
// ---------------------------------------------------------------------------
static __device__ __forceinline__ uint32_t smem_u32(const void* p) {
    uint32_t a;
    asm("{ .reg .u64 t; cvta.to.shared.u64 t, %1; cvt.u32.u64 %0, t; }"
        : "=r"(a) : "l"(p));
    return a;
}
static __device__ __forceinline__ float ex2f(float x) {
    float y;
    asm("ex2.approx.ftz.f32 %0, %1;" : "=f"(y) : "f"(x));
    return y;
}
static __device__ __forceinline__ void cp16(uint32_t dst, const void* src) {
    asm volatile("cp.async.cg.shared.global [%0], [%1], 16;"
                 :: "r"(dst), "l"(src) : "memory");
}
#define CP_COMMIT() asm volatile("cp.async.commit_group;" ::: "memory")
#define CP_WAIT(n)  asm volatile("cp.async.wait_group %0;" :: "n"(n) : "memory")

static __device__ __forceinline__ void ldmatrix_x4(
    uint32_t& r0, uint32_t& r1, uint32_t& r2, uint32_t& r3, uint32_t addr) {
    asm volatile("ldmatrix.sync.aligned.m8n8.x4.shared.b16 {%0,%1,%2,%3}, [%4];"
                 : "=r"(r0), "=r"(r1), "=r"(r2), "=r"(r3) : "r"(addr));
}
static __device__ __forceinline__ void mma16832(
    float* d, const uint32_t* a, const uint32_t* b) {
    asm volatile(
        "mma.sync.aligned.m16n8k32.row.col.f32.e4m3.e4m3.f32 "
        "{%0,%1,%2,%3}, {%4,%5,%6,%7}, {%8,%9}, {%0,%1,%2,%3};"
        : "+f"(d[0]), "+f"(d[1]), "+f"(d[2]), "+f"(d[3])
        : "r"(a[0]), "r"(a[1]), "r"(a[2]), "r"(a[3]), "r"(b[0]), "r"(b[1]));
}
static __device__ __forceinline__ uint32_t pack_fp8x4(
    float a, float b, float c, float d) {
    const __nv_fp8x2_storage_t lo =
        __nv_cvt_float2_to_fp8x2(make_float2(a, b), __NV_SATFINITE, __NV_E4M3);
    const __nv_fp8x2_storage_t hi =
        __nv_cvt_float2_to_fp8x2(make_float2(c, d), __NV_SATFINITE, __NV_E4M3);
    return (uint32_t)lo | ((uint32_t)hi << 16);
}

// tid 0 spins; caller must follow with __syncthreads() before consuming.
static __device__ __forceinline__ void wait_blocks_t0(int xb, int yb, int tid) {
    if (tid == 0) {
        volatile int* c = g_cnt;
        while (c[xb] != 128) {}
        while (c[yb] != 128) {}
        __threadfence();
    }
}

static __device__ __forceinline__ void load_chunk(
    uint32_t sbase, int stage, int chunk,
    const uint8_t* gA, const uint8_t* gB, int tid) {
    const uint32_t aBase = sbase + (uint32_t)(stage * STAGE_BYTES);
    const uint32_t bBase = aBase + (uint32_t)(BM * RS);
#pragma unroll
    for (int r = 0; r < 2; ++r) {
        const int idx = tid + r * 512;
        const int row = idx >> 3, c = idx & 7;
        cp16(aBase + (uint32_t)(row * RS + c * 16),
             gA + (size_t)(chunk * BK) + (size_t)row * DDIM + c * 16);
        cp16(bBase + (uint32_t)(row * RS + c * 16),
             gB + (size_t)(chunk * BK) + (size_t)row * DDIM + c * 16);
    }
    CP_COMMIT();
}

// load one kk-step's A fragments (2x ldmatrix.x4) and B fragments (2x)
static __device__ __forceinline__ void load_frags(
    uint32_t aAddr0, uint32_t bAddr0, uint32_t kb,
    uint32_t a[2][4], uint32_t b[4][2]) {
#pragma unroll
    for (int mi = 0; mi < 2; ++mi)
        ldmatrix_x4(a[mi][0], a[mi][1], a[mi][2], a[mi][3],
                    aAddr0 + kb + (uint32_t)(mi * 16 * RS));
#pragma unroll
    for (int p2 = 0; p2 < 2; ++p2) {
        uint32_t r0, r1, r2, r3;
        ldmatrix_x4(r0, r1, r2, r3, bAddr0 + kb + (uint32_t)(p2 * 16 * RS));
        b[2 * p2][0] = r0; b[2 * p2 + 1][0] = r1;
        b[2 * p2][1] = r2; b[2 * p2 + 1][1] = r3;
    }
}

// ---------------------------------------------------------------------------
// The fused persistent kernel: grid = 148 x 512 threads
// ---------------------------------------------------------------------------
__global__ void __launch_bounds__(512, 1) fused_kernel(
    const float* __restrict__ x, const float* __restrict__ y,
    float* __restrict__ out) {
    extern __shared__ uint8_t smem[];
    __shared__ float part[4][4][3];     // 4 rows x 4 warps-per-row x {sx,sy,sxy}
    __shared__ int sdone;
    const uint32_t sbase = smem_u32(smem);
    const int tid = threadIdx.x;
    const int lane = tid & 31;
    const int wid = tid >> 5;

    // ===== Phase A: normalize + quantize (4 rows per iteration, 128t/row) ===
    {
        const int rg = tid >> 7;            // row-in-group 0..3
        const int pos = tid & 127;          // thread within row
        const int wir = pos >> 5;           // warp-in-row 0..3
        for (int base = blockIdx.x * 4; base < BROWS; base += NSM * 4) {
            const int r = base + rg;
            const bool live = (r < BROWS);
            float4 x0, x1, y0, y1;
            if (live) {
                const float4* xr = reinterpret_cast<const float4*>(x) + (size_t)r * 256;
                const float4* yr = reinterpret_cast<const float4*>(y) + (size_t)r * 256;
                x0 = xr[pos]; x1 = xr[pos + 128];
                y0 = yr[pos]; y1 = yr[pos + 128];
                float ssx = x0.x * x0.x + x0.y * x0.y + x0.z * x0.z + x0.w * x0.w
                          + x1.x * x1.x + x1.y * x1.y + x1.z * x1.z + x1.w * x1.w;
                float ssy = y0.x * y0.x + y0.y * y0.y + y0.z * y0.z + y0.w * y0.w
                          + y1.x * y1.x + y1.y * y1.y + y1.z * y1.z + y1.w * y1.w;
                float sxy = x0.x * y0.x + x0.y * y0.y + x0.z * y0.z + x0.w * y0.w
                          + x1.x * y1.x + x1.y * y1.y + x1.z * y1.z + x1.w * y1.w;
#pragma unroll
                for (int m = 16; m; m >>= 1) {
                    ssx += __shfl_xor_sync(0xffffffffu, ssx, m);
                    ssy += __shfl_xor_sync(0xffffffffu, ssy, m);
                    sxy += __shfl_xor_sync(0xffffffffu, sxy, m);
                }
                if (lane == 0) {
                    part[rg][wir][0] = ssx;
                    part[rg][wir][1] = ssy;
                    part[rg][wir][2] = sxy;
                }
            }
            __syncthreads();
            if (live) {
                const float a = part[rg][0][0] + part[rg][1][0]
                              + part[rg][2][0] + part[rg][3][0];
                const float b = part[rg][0][1] + part[rg][1][1]
                              + part[rg][2][1] + part[rg][3][1];
                const float c = part[rg][0][2] + part[rg][1][2]
                              + part[rg][2][2] + part[rg][3][2];
                const float invx = 1.0f / fmaxf(sqrtf(a), EPSF);
                const float invy = 1.0f / fmaxf(sqrtf(b), EPSF);
                if (pos == 0) {
                    g_diag[r] = c * invx * invy;
                    g_rowsum[r] = 0.f;
                    g_colsum[r] = 0.f;
                }
                const float qx = QSCALE * invx, qy = QSCALE * invy;
                uint32_t* ox = reinterpret_cast<uint32_t*>(g_xq + (size_t)r * DDIM);
                uint32_t* oy = reinterpret_cast<uint32_t*>(g_yq + (size_t)r * DDIM);
                ox[pos]       = pack_fp8x4(x0.x * qx, x0.y * qx, x0.z * qx, x0.w * qx);
                ox[pos + 128] = pack_fp8x4(x1.x * qx, x1.y * qx, x1.z * qx, x1.w * qx);
                oy[pos]       = pack_fp8x4(y0.x * qy, y0.y * qy, y0.z * qy, y0.w * qy);
                oy[pos + 128] = pack_fp8x4(y1.x * qy, y1.y * qy, y1.z * qy, y1.w * qy);
                __threadfence();
            }
            __syncthreads();    // all row stores fenced; partials reusable
            if (live && pos == 0) atomicAdd(&g_cnt[r >> 7], 1);
        }
    }

    // ================= Phase B: persistent GEMM (R14 body) ==================
    const int warp_m = wid & 3;
    const int warp_n = wid >> 2;
    const int gid = lane >> 2, tig = lane & 3;
    const uint32_t lrow = (uint32_t)(lane & 15);
    const uint32_t koff = (uint32_t)((lane >> 4) * 16);

    int t = blockIdx.x;
    const uint8_t* gA = g_xq + (size_t)((t & 31) * BM) * DDIM;
    const uint8_t* gB = g_yq + (size_t)((t >> 5) * BN) * DDIM;

    wait_blocks_t0(t & 31, t >> 5, tid);
    __syncthreads();
    load_chunk(sbase, 0, 0, gA, gB, tid);
    load_chunk(sbase, 1, 1, gA, gB, tid);
    load_chunk(sbase, 2, 2, gA, gB, tid);

    while (true) {
        const int i_base = (t & 31) * BM;
        const int j_base = (t >> 5) * BN;
        const int nxt = t + NSM;
        const bool has_nxt = (nxt < NTILES);
        const uint8_t* gA2 = g_xq + (size_t)((nxt & 31) * BM) * DDIM;
        const uint8_t* gB2 = g_yq + (size_t)((nxt >> 5) * BN) * DDIM;

        float acc[2][4][4];
#pragma unroll
        for (int mi = 0; mi < 2; ++mi)
#pragma unroll
            for (int ni = 0; ni < 4; ++ni)
#pragma unroll
                for (int r = 0; r < 4; ++r) acc[mi][ni][r] = 0.f;

        for (int kt = 0; kt < KT; ++kt) {
            CP_WAIT(STAGES - 2);
            __syncthreads();
            const int p = kt + STAGES - 1;
            if (p < KT) {
                load_chunk(sbase, p & 3, p, gA, gB, tid);
            } else if (has_nxt) {
                if (kt == 5) {
                    wait_blocks_t0(nxt & 31, nxt >> 5, tid);
                    __syncthreads();
                }
                load_chunk(sbase, p & 3, p - KT, gA2, gB2, tid);
            } else {
                CP_COMMIT();
            }

            const uint32_t aTile = sbase + (uint32_t)((kt & 3) * STAGE_BYTES);
            const uint32_t bTile = aTile + (uint32_t)(BM * RS);
            const uint32_t aAddr0 = aTile + (warp_m * 32 + lrow) * RS + koff;
            const uint32_t bAddr0 = bTile + (warp_n * 32 + lrow) * RS + koff;

            uint32_t a[2][2][4], b[2][4][2];
            load_frags(aAddr0, bAddr0, 0, a[0], b[0]);   // prefetch kk=0

#pragma unroll
            for (int kk = 0; kk < 4; ++kk) {
                const int cur = kk & 1;
                if (kk < 3)
                    load_frags(aAddr0, bAddr0, (uint32_t)((kk + 1) * 32),
                               a[cur ^ 1], b[cur ^ 1]);
#pragma unroll
                for (int mi = 0; mi < 2; ++mi)
#pragma unroll
                    for (int ni = 0; ni < 4; ++ni)
                        mma16832(acc[mi][ni], a[cur][mi], b[cur][ni]);
            }
        }

        // -------- fused epilogue: exp + row/col sums --------
        float rs[2][2] = {{0.f, 0.f}, {0.f, 0.f}};
        float cs[4][2];
#pragma unroll
        for (int ni = 0; ni < 4; ++ni) { cs[ni][0] = 0.f; cs[ni][1] = 0.f; }

#pragma unroll
        for (int mi = 0; mi < 2; ++mi)
#pragma unroll
            for (int ni = 0; ni < 4; ++ni) {
                const float e0 = ex2f(acc[mi][ni][0] * K2LOG_S);
                const float e1 = ex2f(acc[mi][ni][1] * K2LOG_S);
                const float e2 = ex2f(acc[mi][ni][2] * K2LOG_S);
                const float e3 = ex2f(acc[mi][ni][3] * K2LOG_S);
                rs[mi][0] += e0 + e1;
                rs[mi][1] += e2 + e3;
                cs[ni][0] += e0 + e2;
                cs[ni][1] += e1 + e3;
            }

        const int m0 = i_base + warp_m * 32;
        const int n0 = j_base + warp_n * 32;
#pragma unroll
        for (int mi = 0; mi < 2; ++mi)
#pragma unroll
            for (int h = 0; h < 2; ++h) {
                float v = rs[mi][h];
                v += __shfl_xor_sync(0xffffffffu, v, 1);
                v += __shfl_xor_sync(0xffffffffu, v, 2);
                if (tig == 0)
                    atomicAdd(&g_rowsum[m0 + mi * 16 + h * 8 + gid], v);
            }
#pragma unroll
        for (int ni = 0; ni < 4; ++ni)
#pragma unroll
            for (int h = 0; h < 2; ++h) {
                float v = cs[ni][h];
                v += __shfl_xor_sync(0xffffffffu, v, 4);
                v += __shfl_xor_sync(0xffffffffu, v, 8);
                v += __shfl_xor_sync(0xffffffffu, v, 16);
                if (gid == 0)
                    atomicAdd(&g_colsum[n0 + ni * 8 + 2 * tig + h], v);
            }

        if (!has_nxt) break;
        t = nxt;
        gA = gA2;
        gB = gB2;
    }

    // ================= Phase C: last CTA finalizes + resets =================
    __threadfence();
    __syncthreads();
    if (tid == 0) sdone = (atomicAdd(&g_done, 1) == NSM - 1) ? 1 : 0;
    __syncthreads();
    if (sdone) {
        __threadfence();
        const float extra = (float)BROWS * 1e-6f + 1e-6f;
        float acc = 0.f;
#pragma unroll
        for (int i = tid; i < BROWS; i += 512) {
            acc += (2.0f / 0.07f) * g_diag[i]
                 - logf(g_rowsum[i] + extra)
                 - logf(g_colsum[i] + extra);
        }
        float* sb = reinterpret_cast<float*>(smem);
        sb[tid] = acc;
        __syncthreads();
#pragma unroll
        for (int s = 256; s; s >>= 1) {
            if (tid < s) sb[tid] += sb[tid + s];
            __syncthreads();
        }
        if (tid == 0) out[0] = sb[0] * (-1.0f / (2.0f * (float)BROWS));
        // reset handshake state for the next graph replay
        if (tid < 32) g_cnt[tid] = 0;
        if (tid == 0) g_done = 0;
    }
}

// ---------------------------------------------------------------------------
extern "C" void kernel_launch(void* const* d_in, const int* in_sizes, int n_in,
                              void* d_out, int out_size) {
    const float* x = (const float*)d_in[0];
    const float* y = (const float*)d_in[1];
    float* out = (float*)d_out;

    static int configured = 0;
    if (!configured) {
        cudaFuncSetAttribute(fused_kernel,
                             cudaFuncAttributeMaxDynamicSharedMemorySize, SMEM_BYTES);
        configured = 1;
    }

    fused_kernel<<<NSM, 512, SMEM_BYTES>>>(x, y, out);
}

// round 17
// speedup vs baseline: 1.3378x; 1.2247x over previous
#include <cuda_runtime.h>
#include <cuda_fp8.h>
#include <cstdint>
#include <math.h>

// ---------------------------------------------------------------------------
// Problem constants (fixed shapes: x,y = [4096,1024] fp32, scalar output)
// ---------------------------------------------------------------------------
#define BROWS 4096
#define DDIM  1024
#define EPSF  1e-6f

// fp8 quantization pre-scale: e4m3 of 16*component; acc = 256*S.
// exp(S/tau) = exp2(acc * log2(e) / (0.07 * 256))
#define QSCALE 16.0f
#define K2LOG_S (20.6099287984152302f / 256.0f)

// R16 analysis: GEMM chunks are LDGSTS-issue-bound (512 cp.async x rt8 =
// 4096 cyc/SMSP/chunk vs QMMA 1856). R17: cp.async.bulk (sm_90 PTX, not
// 'a'-gated) copies each 16KB tile with ONE instruction; quantized data is
// stored PRE-SWIZZLED in tile-major layout so bulk's linear copy lands in
// ldmatrix-ready form (R8-validated XOR swizzle). mbarrier pipeline, parity
// = (kt>>2)&1 (tile-invariant).
#define BM 128
#define BN 128
#define BK 128
#define KT 8
#define TILE_B 16384                       // one 128x128B swizzled tile
#define STAGE_B (2 * TILE_B)               // A tile + B tile
#define SMEM_BYTES (4 * STAGE_B)           // 131072
#define NSM 148
#define NTILES 1024
#define NWARPG (NSM * 16)

// ---------------------------------------------------------------------------
// Scratch (device globals: allocation-free rule; zero-initialized)
// g_xq/g_yq layout: [block 0..31][chunk 0..7][swizzled 128x128B tile]
// ---------------------------------------------------------------------------
__device__ uint8_t g_xq[(size_t)BROWS * DDIM];
__device__ uint8_t g_yq[(size_t)BROWS * DDIM];
__device__ float g_rowsum[BROWS];
__device__ float g_colsum[BROWS];
__device__ float g_diag[BROWS];
__device__ int g_cnt[32];     // row blocks of 128; ==128 when block ready
__device__ int g_done;        // CTA completion counter

// ---------------------------------------------------------------------------
// PTX helpers (<= sm_90 baseline; nothing 'a'-gated)
// ---------------------------------------------------------------------------
static __device__ __forceinline__ uint32_t smem_u32(const void* p) {
    uint32_t a;
    asm("{ .reg .u64 t; cvta.to.shared.u64 t, %1; cvt.u32.u64 %0, t; }"
        : "=r"(a) : "l"(p));
    return a;
}
static __device__ __forceinline__ float ex2f(float x) {
    float y;
    asm("ex2.approx.ftz.f32 %0, %1;" : "=f"(y) : "f"(x));
    return y;
}

#define MBARRIER_INIT(addr, cnt) \
    asm volatile("mbarrier.init.shared.b64 [%0], %1;" \
                 :: "r"((uint32_t)(addr)), "r"((uint32_t)(cnt)) : "memory")
#define MBARRIER_EXPECT_TX(addr, bytes) \
    asm volatile("mbarrier.arrive.expect_tx.shared.b64 _, [%0], %1;" \
                 :: "r"((uint32_t)(addr)), "r"((uint32_t)(bytes)) : "memory")
#define MBARRIER_WAIT_PARITY(mbar_addr, phase_parity) do {                    \
    uint32_t _mbar = (uint32_t)(mbar_addr);                                   \
    uint32_t _par  = (uint32_t)(phase_parity);                                \
    uint32_t _done;                                                           \
    asm volatile(                                                             \
        "{\n\t.reg .pred p;\n\t"                                              \
        "mbarrier.try_wait.parity.acquire.cta.shared::cta.b64 p, [%1], %2;\n\t" \
        "selp.b32 %0, 1, 0, p;\n\t}"                                          \
        : "=r"(_done) : "r"(_mbar), "r"(_par) : "memory");                    \
    if (!_done) {                                                             \
        asm volatile(                                                         \
            "{\n\t.reg .pred P1;\n\t"                                         \
            "WAIT_LOOP_%=:\n\t"                                               \
            "mbarrier.try_wait.parity.acquire.cta.shared::cta.b64 P1, [%0], %1, 0x989680;\n\t" \
            "@P1 bra.uni WAIT_DONE_%=;\n\t"                                   \
            "bra.uni WAIT_LOOP_%=;\n\t"                                       \
            "WAIT_DONE_%=:\n\t}"                                              \
            :: "r"(_mbar), "r"(_par) : "memory");                             \
    }                                                                         \
} while (0)

static __device__ __forceinline__ void bulk16k(
    uint32_t dst, const uint8_t* src, uint32_t mbar) {
    asm volatile(
        "cp.async.bulk.shared::cta.global.mbarrier::complete_tx::bytes "
        "[%0], [%1], %2, [%3];"
        :: "r"(dst), "l"(src), "r"((uint32_t)TILE_B), "r"(mbar) : "memory");
}

static __device__ __forceinline__ void ldmatrix_x4(
    uint32_t& r0, uint32_t& r1, uint32_t& r2, uint32_t& r3, uint32_t addr) {
    asm volatile("ldmatrix.sync.aligned.m8n8.x4.shared.b16 {%0,%1,%2,%3}, [%4];"
                 : "=r"(r0), "=r"(r1), "=r"(r2), "=r"(r3) : "r"(addr));
}
static __device__ __forceinline__ void mma16832(
    float* d, const uint32_t* a, const uint32_t* b) {
    asm volatile(
        "mma.sync.aligned.m16n8k32.row.col.f32.e4m3.e4m3.f32 "
        "{%0,%1,%2,%3}, {%4,%5,%6,%7}, {%8,%9}, {%0,%1,%2,%3};"
        : "+f"(d[0]), "+f"(d[1]), "+f"(d[2]), "+f"(d[3])
        : "r"(a[0]), "r"(a[1]), "r"(a[2]), "r"(a[3]), "r"(b[0]), "r"(b[1]));
}
static __device__ __forceinline__ uint32_t pack_fp8x4(
    float a, float b, float c, float d) {
    const __nv_fp8x2_storage_t lo =
        __nv_cvt_float2_to_fp8x2(make_float2(a, b), __NV_SATFINITE, __NV_E4M3);
    const __nv_fp8x2_storage_t hi =
        __nv_cvt_float2_to_fp8x2(make_float2(c, d), __NV_SATFINITE, __NV_E4M3);
    return (uint32_t)lo | ((uint32_t)hi << 16);
}

// ---------------------------------------------------------------------------
// The fused persistent kernel: grid = 148 x 512 threads
// ---------------------------------------------------------------------------
__global__ void __launch_bounds__(512, 1) fused_kernel(
    const float* __restrict__ x, const float* __restrict__ y,
    float* __restrict__ out) {
    extern __shared__ uint8_t smem[];
    __shared__ uint64_t mbar[4];
    __shared__ int sdone;
    const uint32_t sbase = smem_u32(smem);
    const uint32_t mb0 = smem_u32(&mbar[0]);
    const int tid = threadIdx.x;
    const int lane = tid & 31;
    const int wid = tid >> 5;

    // ========== Phase A: normalize + quantize (R14 warp-per-row) ===========
    // Stores go to the tile-major pre-swizzled layout.
    for (int r = blockIdx.x * 16 + wid; r < BROWS; r += NWARPG) {
        const float4* xr = reinterpret_cast<const float4*>(x) + (size_t)r * 256;
        const float4* yr = reinterpret_cast<const float4*>(y) + (size_t)r * 256;
        float4 xv[8], yv[8];
#pragma unroll
        for (int u = 0; u < 8; ++u) xv[u] = xr[lane + 32 * u];
#pragma unroll
        for (int u = 0; u < 8; ++u) yv[u] = yr[lane + 32 * u];

        float ssx = 0.f, ssy = 0.f, sxy = 0.f;
#pragma unroll
        for (int u = 0; u < 8; ++u) {
            ssx += xv[u].x * xv[u].x + xv[u].y * xv[u].y
                 + xv[u].z * xv[u].z + xv[u].w * xv[u].w;
            ssy += yv[u].x * yv[u].x + yv[u].y * yv[u].y
                 + yv[u].z * yv[u].z + yv[u].w * yv[u].w;
            sxy += xv[u].x * yv[u].x + xv[u].y * yv[u].y
                 + xv[u].z * yv[u].z + xv[u].w * yv[u].w;
        }
#pragma unroll
        for (int m = 16; m; m >>= 1) {
            ssx += __shfl_xor_sync(0xffffffffu, ssx, m);
            ssy += __shfl_xor_sync(0xffffffffu, ssy, m);
            sxy += __shfl_xor_sync(0xffffffffu, sxy, m);
        }
        const float invx = 1.0f / fmaxf(sqrtf(ssx), EPSF);
        const float invy = 1.0f / fmaxf(sqrtf(ssy), EPSF);
        if (lane == 0) {
            g_diag[r] = sxy * invx * invy;
            g_rowsum[r] = 0.f;
            g_colsum[r] = 0.f;
        }
        const float qx = QSCALE * invx, qy = QSCALE * invy;
        // swizzled in-tile offset for this thread's u32 (16B unit = lane>>2)
        const uint32_t so = (uint32_t)((r & 127) * 128)
                          + ((uint32_t)(((lane >> 2) ^ (r & 7)) & 7) << 4)
                          + (uint32_t)((lane & 3) * 4);
        uint8_t* xt = g_xq + (size_t)((r >> 7) * 8) * TILE_B;
        uint8_t* yt = g_yq + (size_t)((r >> 7) * 8) * TILE_B;
#pragma unroll
        for (int u = 0; u < 8; ++u) {     // chunk u holds k = 128u..128u+127
            *reinterpret_cast<uint32_t*>(xt + (size_t)u * TILE_B + so) =
                pack_fp8x4(xv[u].x * qx, xv[u].y * qx, xv[u].z * qx, xv[u].w * qx);
            *reinterpret_cast<uint32_t*>(yt + (size_t)u * TILE_B + so) =
                pack_fp8x4(yv[u].x * qy, yv[u].y * qy, yv[u].z * qy, yv[u].w * qy);
        }
        __threadfence();
        if (lane == 0) atomicAdd(&g_cnt[r >> 7], 1);
    }

    // ================= Phase B: persistent GEMM with bulk-copy pipeline =====
    const int warp_m = wid & 3;
    const int warp_n = wid >> 2;
    const int gid = lane >> 2, tig = lane & 3;
    const uint32_t lrow = (uint32_t)(lane & 15);
    const uint32_t khalf = (uint32_t)(lane >> 4);   // 16B-unit low bit

    // per-thread swizzle constants for ldmatrix addressing
    uint32_t rAoff[2], rAs[2], rBoff[2], rBs[2];
#pragma unroll
    for (int mi = 0; mi < 2; ++mi) {
        const uint32_t row = (uint32_t)(warp_m * 32 + mi * 16) + lrow;
        rAoff[mi] = row * 128;
        rAs[mi] = row & 7;
    }
#pragma unroll
    for (int p2 = 0; p2 < 2; ++p2) {
        const uint32_t row = (uint32_t)(warp_n * 32 + p2 * 16) + lrow;
        rBoff[p2] = row * 128;
        rBs[p2] = row & 7;
    }

    int t = blockIdx.x;

    if (tid == 0) {
#pragma unroll
        for (int s = 0; s < 4; ++s) MBARRIER_INIT(mb0 + 8 * s, 1);
    }
    __syncthreads();     // mbarrier init visible before any try_wait

    if (tid == 0) {
        // wait for this tile's blocks, then issue chunks 0..2
        volatile int* c = g_cnt;
        const int xb = t & 31, yb = t >> 5;
        while (c[xb] != 128) {}
        while (c[yb] != 128) {}
        __threadfence();
#pragma unroll
        for (int s = 0; s < 3; ++s) {
            MBARRIER_EXPECT_TX(mb0 + 8 * s, STAGE_B);
            bulk16k(sbase + s * STAGE_B,
                    g_xq + (size_t)(xb * 8 + s) * TILE_B, mb0 + 8 * s);
            bulk16k(sbase + s * STAGE_B + TILE_B,
                    g_yq + (size_t)(yb * 8 + s) * TILE_B, mb0 + 8 * s);
        }
    }

    while (true) {
        const int i_base = (t & 31) * BM;
        const int j_base = (t >> 5) * BN;
        const int nxt = t + NSM;
        const bool has_nxt = (nxt < NTILES);

        float acc[2][4][4];
#pragma unroll
        for (int mi = 0; mi < 2; ++mi)
#pragma unroll
            for (int ni = 0; ni < 4; ++ni)
#pragma unroll
                for (int r = 0; r < 4; ++r) acc[mi][ni][r] = 0.f;

        for (int kt = 0; kt < KT; ++kt) {
            MBARRIER_WAIT_PARITY(mb0 + 8 * (kt & 3), (kt >> 2) & 1);
            __syncthreads();   // all warps done with stage (kt+4)&3's old data
            if (tid == 0) {
                const int p = kt + 3;
                const int s = p & 3;
                if (p < KT) {
                    MBARRIER_EXPECT_TX(mb0 + 8 * s, STAGE_B);
                    bulk16k(sbase + s * STAGE_B,
                            g_xq + (size_t)((t & 31) * 8 + p) * TILE_B, mb0 + 8 * s);
                    bulk16k(sbase + s * STAGE_B + TILE_B,
                            g_yq + (size_t)((t >> 5) * 8 + p) * TILE_B, mb0 + 8 * s);
                } else if (has_nxt) {
                    if (kt == 5) {   // first next-tile issue: readiness check
                        volatile int* c = g_cnt;
                        while (c[nxt & 31] != 128) {}
                        while (c[nxt >> 5] != 128) {}
                        __threadfence();
                    }
                    MBARRIER_EXPECT_TX(mb0 + 8 * s, STAGE_B);
                    bulk16k(sbase + s * STAGE_B,
                            g_xq + (size_t)((nxt & 31) * 8 + (p - KT)) * TILE_B,
                            mb0 + 8 * s);
                    bulk16k(sbase + s * STAGE_B + TILE_B,
                            g_yq + (size_t)((nxt >> 5) * 8 + (p - KT)) * TILE_B,
                            mb0 + 8 * s);
                }
            }

            const uint32_t aTile = sbase + (uint32_t)((kt & 3) * STAGE_B);
            const uint32_t bTile = aTile + TILE_B;

            // fragment double-buffered inner loop (R14)
            uint32_t a[2][2][4], b[2][4][2];
            {
                const uint32_t ch = khalf;            // kk=0
#pragma unroll
                for (int mi = 0; mi < 2; ++mi)
                    ldmatrix_x4(a[0][mi][0], a[0][mi][1], a[0][mi][2], a[0][mi][3],
                                aTile + rAoff[mi] + ((ch ^ rAs[mi]) << 4));
#pragma unroll
                for (int p2 = 0; p2 < 2; ++p2) {
                    uint32_t r0, r1, r2, r3;
                    ldmatrix_x4(r0, r1, r2, r3,
                                bTile + rBoff[p2] + ((ch ^ rBs[p2]) << 4));
                    b[0][2 * p2][0] = r0; b[0][2 * p2 + 1][0] = r1;
                    b[0][2 * p2][1] = r2; b[0][2 * p2 + 1][1] = r3;
                }
            }
#pragma unroll
            for (int kk = 0; kk < 4; ++kk) {
                const int cur = kk & 1;
                if (kk < 3) {
                    const uint32_t ch = (uint32_t)((kk + 1) * 2) + khalf;
#pragma unroll
                    for (int mi = 0; mi < 2; ++mi)
                        ldmatrix_x4(a[cur ^ 1][mi][0], a[cur ^ 1][mi][1],
                                    a[cur ^ 1][mi][2], a[cur ^ 1][mi][3],
                                    aTile + rAoff[mi] + ((ch ^ rAs[mi]) << 4));
#pragma unroll
                    for (int p2 = 0; p2 < 2; ++p2) {
                        uint32_t r0, r1, r2, r3;
                        ldmatrix_x4(r0, r1, r2, r3,
                                    bTile + rBoff[p2] + ((ch ^ rBs[p2]) << 4));
                        b[cur ^ 1][2 * p2][0] = r0; b[cur ^ 1][2 * p2 + 1][0] = r1;
                        b[cur ^ 1][2 * p2][1] = r2; b[cur ^ 1][2 * p2 + 1][1] = r3;
                    }
                }
#pragma unroll
                for (int mi = 0; mi < 2; ++mi)
#pragma unroll
                    for (int ni = 0; ni < 4; ++ni)
                        mma16832(acc[mi][ni], a[cur][mi], b[cur][ni]);
            }
        }

        // -------- fused epilogue: exp + row/col sums --------
        float rs[2][2] = {{0.f, 0.f}, {0.f, 0.f}};
        float cs[4][2];
#pragma unroll
        for (int ni = 0; ni < 4; ++ni) { cs[ni][0] = 0.f; cs[ni][1] = 0.f; }

#pragma unroll
        for (int mi = 0; mi < 2; ++mi)
#pragma unroll
            for (int ni = 0; ni < 4; ++ni) {
                const float e0 = ex2f(acc[mi][ni][0] * K2LOG_S);
                const float e1 = ex2f(acc[mi][ni][1] * K2LOG_S);
                const float e2 = ex2f(acc[mi][ni][2] * K2LOG_S);
                const float e3 = ex2f(acc[mi][ni][3] * K2LOG_S);
                rs[mi][0] += e0 + e1;
                rs[mi][1] += e2 + e3;
                cs[ni][0] += e0 + e2;
                cs[ni][1] += e1 + e3;
            }

        const int m0 = i_base + warp_m * 32;
        const int n0 = j_base + warp_n * 32;
#pragma unroll
        for (int mi = 0; mi < 2; ++mi)
#pragma unroll
            for (int h = 0; h < 2; ++h) {
                float v = rs[mi][h];
                v += __shfl_xor_sync(0xffffffffu, v, 1);
                v += __shfl_xor_sync(0xffffffffu, v, 2);
                if (tig == 0)
                    atomicAdd(&g_rowsum[m0 + mi * 16 + h * 8 + gid], v);
            }
#pragma unroll
        for (int ni = 0; ni < 4; ++ni)
#pragma unroll
            for (int h = 0; h < 2; ++h) {
                float v = cs[ni][h];
                v += __shfl_xor_sync(0xffffffffu, v, 4);
                v += __shfl_xor_sync(0xffffffffu, v, 8);
                v += __shfl_xor_sync(0xffffffffu, v, 16);
                if (gid == 0)
                    atomicAdd(&g_colsum[n0 + ni * 8 + 2 * tig + h], v);
            }

        if (!has_nxt) break;
        t = nxt;
    }

    // ================= Phase C: last CTA finalizes + resets =================
    __threadfence();
    __syncthreads();
    if (tid == 0) sdone = (atomicAdd(&g_done, 1) == NSM - 1) ? 1 : 0;
    __syncthreads();
    if (sdone) {
        __threadfence();
        const float extra = (float)BROWS * 1e-6f + 1e-6f;
        float acc = 0.f;
#pragma unroll
        for (int i = tid; i < BROWS; i += 512) {
            acc += (2.0f / 0.07f) * g_diag[i]
                 - logf(g_rowsum[i] + extra)
                 - logf(g_colsum[i] + extra);
        }
        float* sb = reinterpret_cast<float*>(smem);
        sb[tid] = acc;
        __syncthreads();
#pragma unroll
        for (int s = 256; s; s >>= 1) {
            if (tid < s) sb[tid] += sb[tid + s];
            __syncthreads();
        }
        if (tid == 0) out[0] = sb[0] * (-1.0f / (2.0f * (float)BROWS));
        // reset handshake state for the next graph replay
        if (tid < 32) g_cnt[tid] = 0;
        if (tid == 0) g_done = 0;
    }
}

// ---------------------------------------------------------------------------
extern "C" void kernel_launch(void* const* d_in, const int* in_sizes, int n_in,
                              void* d_out, int out_size) {
    const float* x = (const float*)d_in[0];
    const float* y = (const float*)d_in[1];
    float* out = (float*)d_out;

    static int configured = 0;
    if (!configured) {
        cudaFuncSetAttribute(fused_kernel,
                             cudaFuncAttributeMaxDynamicSharedMemorySize, SMEM_BYTES);
        configured = 1;
    }

    fused_kernel<<<NSM, 512, SMEM_BYTES>>>(x, y, out);
}